// round 10
// baseline (speedup 1.0000x reference)
#include <cuda_runtime.h>
#include <cuda_bf16.h>
#include <cstdint>

#define B_ROWS 32768
#define C_COLS 1000
#define C_PAD  1024
#define F_DIM  256

#define BMR     64      // feature rows per CTA
#define BNP     512     // proto cols per CTA (cluster of 2 covers 1024)
#define KC      64      // k-chunk
#define NKC     4       // 256 / 64
#define THREADS 512     // 16 warps

// SMEM layout (bytes)
#define SM_FEAT  0                        // 64 rows x 512B swizzled      = 32KB
#define SM_SROW  32768                    // 64 floats (own partial sums)
#define SM_SMEAN 33024                    // 64 floats (combined means)
#define SM_B0    33792                    // proto chunk: 512 x 128B      = 64KB
#define SM_B1    (33792 + 65536)
#define SM_STAGE 33792                    // reuses B0+B1: 64 x 2048B     = 128KB
#define SM_TOTAL (33792 + 131072)         // 164864

// Scratch (device global — no allocation allowed)
__device__ __align__(16) __nv_bfloat16 g_Pn[(size_t)C_PAD * F_DIM];

// ---------------------------------------------------------------------------
// helpers
// ---------------------------------------------------------------------------
__device__ __forceinline__ uint32_t smem_u32(const void* p) {
    uint32_t a;
    asm("{ .reg .u64 t; cvta.to.shared.u64 t, %1; cvt.u32.u64 %0, t; }" : "=r"(a) : "l"(p));
    return a;
}
__device__ __forceinline__ void ldsm_x4(uint32_t* r, uint32_t addr) {
    asm volatile("ldmatrix.sync.aligned.m8n8.x4.shared.b16 {%0,%1,%2,%3}, [%4];\n"
        : "=r"(r[0]), "=r"(r[1]), "=r"(r[2]), "=r"(r[3]) : "r"(addr));
}
__device__ __forceinline__ void mma16816(float* c, const uint32_t* a, uint32_t b0, uint32_t b1) {
    asm volatile(
        "mma.sync.aligned.m16n8k16.row.col.f32.bf16.bf16.f32 "
        "{%0,%1,%2,%3}, {%4,%5,%6,%7}, {%8,%9}, {%0,%1,%2,%3};\n"
        : "+f"(c[0]), "+f"(c[1]), "+f"(c[2]), "+f"(c[3])
        : "r"(a[0]), "r"(a[1]), "r"(a[2]), "r"(a[3]), "r"(b0), "r"(b1));
}
__device__ __forceinline__ float fsqrt_ap(float x) {
    float r; asm("sqrt.approx.f32 %0, %1;" : "=f"(r) : "f"(x)); return r;
}
#define CP_ASYNC16(dst, src) \
    asm volatile("cp.async.cg.shared.global [%0], [%1], 16;" :: "r"(dst), "l"(src))
#define CP_COMMIT() asm volatile("cp.async.commit_group;" ::: "memory")
#define CP_WAIT0()  asm volatile("cp.async.wait_group 0;" ::: "memory")
#define CLUSTER_ARRIVE() asm volatile("barrier.cluster.arrive.aligned;" ::: "memory")
#define CLUSTER_WAIT()   asm volatile("barrier.cluster.wait.aligned;" ::: "memory")

// ---------------------------------------------------------------------------
// Kernel 1: L2-normalize prototypes -> bf16, zero-pad rows [1000,1024)
// ---------------------------------------------------------------------------
__global__ void norm_protos_kernel(const float* __restrict__ proto) {
    int gtid = blockIdx.x * blockDim.x + threadIdx.x;
    int row  = gtid >> 5;
    int lane = gtid & 31;
    if (row >= C_PAD) return;

    if (row >= C_COLS) {
        uint4 z = {0u, 0u, 0u, 0u};
        reinterpret_cast<uint4*>(g_Pn)[row * (F_DIM/8) + lane] = z;
        return;
    }
    const float4* src = reinterpret_cast<const float4*>(proto + (size_t)row * F_DIM);
    float4 v0 = src[lane * 2 + 0];
    float4 v1 = src[lane * 2 + 1];

    float ss = v0.x*v0.x + v0.y*v0.y + v0.z*v0.z + v0.w*v0.w
             + v1.x*v1.x + v1.y*v1.y + v1.z*v1.z + v1.w*v1.w;
    #pragma unroll
    for (int o = 16; o; o >>= 1) ss += __shfl_xor_sync(0xFFFFFFFFu, ss, o);
    float inv = 1.0f / fmaxf(sqrtf(ss), 1e-12f);

    union { __nv_bfloat162 h[4]; uint4 u; } pack;
    pack.h[0] = __floats2bfloat162_rn(v0.x*inv, v0.y*inv);
    pack.h[1] = __floats2bfloat162_rn(v0.z*inv, v0.w*inv);
    pack.h[2] = __floats2bfloat162_rn(v1.x*inv, v1.y*inv);
    pack.h[3] = __floats2bfloat162_rn(v1.z*inv, v1.w*inv);
    reinterpret_cast<uint4*>(g_Pn)[row * (F_DIM/8) + lane] = pack.u;
}

// ---------------------------------------------------------------------------
// Kernel 2: fused normalize(A) + GEMM + epilogue, 2-CTA cluster per row block.
//   CTA = 64 feat rows x 512 protos (cluster rank = blockIdx.x picks half).
//   MMA roles swapped: protos = A-operand (m16), features = B-operand (n8).
//   Warp w: protos [w*32, w*32+32) x ALL 64 features; acc[2][8][4] (64 regs).
//   A (features, 64x256 bf16) normalized in-CTA, full-K smem resident.
//   B (protos) streamed in 4 k-chunks of 64, double-buffered cp.async.
//   Per-feature sums exchanged between cluster CTAs via DSMEM.
//   Output staged in swizzled smem, written coalesced.
// ---------------------------------------------------------------------------
__global__ void __launch_bounds__(THREADS, 1) __cluster_dims__(2, 1, 1)
fused_gemm_kernel(const float* __restrict__ feat,
                  const float* __restrict__ dscale, const float* __restrict__ temp,
                  float* __restrict__ out) {
    extern __shared__ __align__(16) unsigned char smem[];
    const uint32_t smem_base = smem_u32(smem);

    const int tid  = threadIdx.x;
    const int lane = tid & 31;
    const int warp = tid >> 5;
    const int gp0  = blockIdx.x * BNP;           // proto base (0 or 512)
    const int grow = blockIdx.y * BMR;           // feature row base

    float* srow  = reinterpret_cast<float*>(smem + SM_SROW);
    float* smean = reinterpret_cast<float*>(smem + SM_SMEAN);
    if (tid < BMR) srow[tid] = 0.0f;

    // ---- Prefetch proto k-chunk 0 (overlaps feature normalize) ----
    const uint4* gB = reinterpret_cast<const uint4*>(g_Pn);
    {
        #pragma unroll
        for (int it = 0; it < 8; it++) {
            int idx = it * THREADS + tid;        // 0..4095
            int r = idx >> 3, c8 = idx & 7;
            uint32_t dst = smem_base + SM_B0 + r * 128 + ((c8 ^ (r & 7)) << 4);
            CP_ASYNC16(dst, gB + (size_t)(gp0 + r) * 32 + c8);
        }
        CP_COMMIT();
    }

    // ---- Normalize feature rows in-CTA: warp w -> rows 4w..4w+3 ----
    {
        const float4* gF = reinterpret_cast<const float4*>(feat)
                         + (size_t)grow * (F_DIM / 4);
        #pragma unroll
        for (int rr = 0; rr < 4; rr++) {
            int r = warp * 4 + rr;
            float4 v0 = __ldg(&gF[r * 64 + lane * 2 + 0]);
            float4 v1 = __ldg(&gF[r * 64 + lane * 2 + 1]);
            float ss = v0.x*v0.x + v0.y*v0.y + v0.z*v0.z + v0.w*v0.w
                     + v1.x*v1.x + v1.y*v1.y + v1.z*v1.z + v1.w*v1.w;
            #pragma unroll
            for (int o = 16; o; o >>= 1) ss += __shfl_xor_sync(0xFFFFFFFFu, ss, o);
            float inv = 1.0f / fmaxf(sqrtf(ss), 1e-12f);

            union { __nv_bfloat162 h[4]; uint4 u; } pack;
            pack.h[0] = __floats2bfloat162_rn(v0.x*inv, v0.y*inv);
            pack.h[1] = __floats2bfloat162_rn(v0.z*inv, v0.w*inv);
            pack.h[2] = __floats2bfloat162_rn(v1.x*inv, v1.y*inv);
            pack.h[3] = __floats2bfloat162_rn(v1.z*inv, v1.w*inv);
            *reinterpret_cast<uint4*>(smem + SM_FEAT + r * 512 + ((lane ^ (r & 7)) << 4)) = pack.u;
        }
    }
    CP_WAIT0();
    __syncthreads();

    // ---- addressing ----
    // proto (A-operand) frags: rows = warp's protos
    uint32_t pBase[2]; int pXor[2];
    #pragma unroll
    for (int pp = 0; pp < 2; pp++) {
        int prow = warp * 32 + pp * 16 + (lane & 15);
        pBase[pp] = prow * 128;
        pXor[pp]  = prow & 7;
    }
    const int p_h = lane >> 4;

    // feature (B-operand) frags
    const int b_n = (lane & 7) | ((lane & 16) >> 1);
    const int b_h = (lane >> 3) & 1;
    uint32_t fBase[4]; int fXor[4];
    #pragma unroll
    for (int fq = 0; fq < 4; fq++) {
        int frow = fq * 16 + b_n;
        fBase[fq] = smem_base + SM_FEAT + frow * 512;
        fXor[fq]  = frow & 7;
    }

    float acc[2][8][4];
    #pragma unroll
    for (int pp = 0; pp < 2; pp++)
        #pragma unroll
        for (int ff = 0; ff < 8; ff++)
            #pragma unroll
            for (int i = 0; i < 4; i++) acc[pp][ff][i] = 0.0f;

    // ---- Main loop: 4 k-chunks, double-buffered ----
    #pragma unroll
    for (int kc = 0; kc < NKC; kc++) {
        if (kc < NKC - 1) {
            uint32_t nb = smem_base + ((kc & 1) ? SM_B0 : SM_B1);
            #pragma unroll
            for (int it = 0; it < 8; it++) {
                int idx = it * THREADS + tid;
                int r = idx >> 3, c8 = idx & 7;
                CP_ASYNC16(nb + r * 128 + ((c8 ^ (r & 7)) << 4),
                           gB + (size_t)(gp0 + r) * 32 + (kc + 1) * 8 + c8);
            }
            CP_COMMIT();
        }

        uint32_t buf = smem_base + ((kc & 1) ? SM_B1 : SM_B0);

        #pragma unroll
        for (int kk = 0; kk < 4; kk++) {
            uint32_t ap[2][4], fb[4][4];
            #pragma unroll
            for (int pp = 0; pp < 2; pp++)
                ldsm_x4(ap[pp], buf + pBase[pp] + (((2 * kk + p_h) ^ pXor[pp]) << 4));
            int kg = kc * 4 + kk;
            #pragma unroll
            for (int fq = 0; fq < 4; fq++)
                ldsm_x4(fb[fq], fBase[fq] + (((2 * kg + b_h) ^ fXor[fq]) << 4));

            #pragma unroll
            for (int pp = 0; pp < 2; pp++)
                #pragma unroll
                for (int ff = 0; ff < 8; ff++) {
                    int fq = ff >> 1, h = (ff & 1) * 2;
                    mma16816(acc[pp][ff], ap[pp], fb[fq][h], fb[fq][h + 1]);
                }
        }

        if (kc < NKC - 1) {
            CP_WAIT0();
            __syncthreads();
        }
    }

    // ---- Epilogue pass 1: iso + per-feature partial sums (masked protos) ----
    const float ads = fabsf(__ldg(dscale));
    const float it_ = 1.0f / __ldg(temp);

    // global proto index for acc rows (c0/c1: P; c2/c3: P+8)
    bool v0[2], v1[2];
    #pragma unroll
    for (int pp = 0; pp < 2; pp++) {
        int P = gp0 + warp * 32 + pp * 16 + (lane >> 2);
        v0[pp] = (P < C_COLS);
        v1[pp] = (P + 8 < C_COLS);
    }

    #pragma unroll
    for (int ff = 0; ff < 8; ff++) {
        float s0 = 0.0f, s1 = 0.0f;
        #pragma unroll
        for (int pp = 0; pp < 2; pp++) {
            float i0 = ads * fsqrt_ap(fmaxf(1.0f - acc[pp][ff][0], 0.0f));
            float i1 = ads * fsqrt_ap(fmaxf(1.0f - acc[pp][ff][1], 0.0f));
            float i2 = ads * fsqrt_ap(fmaxf(1.0f - acc[pp][ff][2], 0.0f));
            float i3 = ads * fsqrt_ap(fmaxf(1.0f - acc[pp][ff][3], 0.0f));
            acc[pp][ff][0] = i0; acc[pp][ff][1] = i1;
            acc[pp][ff][2] = i2; acc[pp][ff][3] = i3;
            if (v0[pp]) { s0 += i0; s1 += i1; }
            if (v1[pp]) { s0 += i2; s1 += i3; }
        }
        // reduce over protos: lanes {l, l^4, l^8, l^16}
        s0 += __shfl_xor_sync(0xFFFFFFFFu, s0, 4);
        s0 += __shfl_xor_sync(0xFFFFFFFFu, s0, 8);
        s0 += __shfl_xor_sync(0xFFFFFFFFu, s0, 16);
        s1 += __shfl_xor_sync(0xFFFFFFFFu, s1, 4);
        s1 += __shfl_xor_sync(0xFFFFFFFFu, s1, 8);
        s1 += __shfl_xor_sync(0xFFFFFFFFu, s1, 16);
        if (lane < 4) {
            atomicAdd(&srow[ff * 8 + 2 * lane],     s0);
            atomicAdd(&srow[ff * 8 + 2 * lane + 1], s1);
        }
    }
    __syncthreads();

    // ---- Cross-CTA partial-sum exchange via DSMEM ----
    CLUSTER_ARRIVE();
    CLUSTER_WAIT();
    if (tid < BMR) {
        uint32_t local = smem_base + SM_SROW + tid * 4;
        uint32_t peer_rank = blockIdx.x ^ 1;
        uint32_t rem;
        asm("mapa.shared::cluster.u32 %0, %1, %2;" : "=r"(rem) : "r"(local), "r"(peer_rank));
        float pv;
        asm volatile("ld.shared::cluster.f32 %0, [%1];" : "=f"(pv) : "r"(rem));
        smean[tid] = (srow[tid] + pv) * (1.0f / (float)C_COLS);
    }
    CLUSTER_ARRIVE();
    CLUSTER_WAIT();
    __syncthreads();

    // ---- Epilogue pass 2: logits -> swizzled stage ----
    // stage word(f, p) = f*512 + ((p + 4*(f&7)) & 511)
    float* stg = reinterpret_cast<float*>(smem + SM_STAGE);
    const int pl0 = warp * 32 + (lane >> 2);          // local proto for c0/c1
    #pragma unroll
    for (int ff = 0; ff < 8; ff++) {
        int f0 = ff * 8 + 2 * (lane & 3);
        int f1 = f0 + 1;
        float m0 = smean[f0], m1 = smean[f1];
        #pragma unroll
        for (int pp = 0; pp < 2; pp++) {
            int p = pl0 + pp * 16;
            stg[f0 * 512 + ((p     + 4 * (f0 & 7)) & 511)] = -(acc[pp][ff][0] + m0) * it_;
            stg[f1 * 512 + ((p     + 4 * (f1 & 7)) & 511)] = -(acc[pp][ff][1] + m1) * it_;
            stg[f0 * 512 + ((p + 8 + 4 * (f0 & 7)) & 511)] = -(acc[pp][ff][2] + m0) * it_;
            stg[f1 * 512 + ((p + 8 + 4 * (f1 & 7)) & 511)] = -(acc[pp][ff][3] + m1) * it_;
        }
    }
    __syncthreads();

    // ---- Coalesced global write: 64 rows x (512 or 488) cols ----
    const int validP4 = (gp0 + BNP <= C_COLS) ? (BNP / 4) : ((C_COLS - gp0) / 4); // 128 or 122
    #pragma unroll
    for (int i = 0; i < 16; i++) {
        int fidx = i * THREADS + tid;    // 0..8191 over 64 rows x 128 f4
        int f  = fidx >> 7;
        int p4 = fidx & 127;
        if (p4 < validP4) {
            int pw = (4 * p4 + 4 * (f & 7)) & 511;   // 4-aligned word
            float4 v = *reinterpret_cast<float4*>(&stg[f * 512 + pw]);
            *reinterpret_cast<float4*>(out + (size_t)(grow + f) * C_COLS + gp0 + 4 * p4) = v;
        }
    }
}

// ---------------------------------------------------------------------------
extern "C" void kernel_launch(void* const* d_in, const int* in_sizes, int n_in,
                              void* d_out, int out_size) {
    const float* feat  = (const float*)d_in[0];
    const float* proto = (const float*)d_in[1];
    const float* dsc   = (const float*)d_in[2];
    const float* temp  = (const float*)d_in[3];
    float* out = (float*)d_out;

    cudaFuncSetAttribute(fused_gemm_kernel,
                         cudaFuncAttributeMaxDynamicSharedMemorySize, SM_TOTAL);

    norm_protos_kernel<<<C_PAD / 8, 256>>>(proto);
    fused_gemm_kernel<<<dim3(2, B_ROWS / BMR), THREADS, SM_TOTAL>>>(feat, dsc, temp, out);
}